// round 11
// baseline (speedup 1.0000x reference)
#include <cuda_runtime.h>
#include <stdint.h>
#include <math.h>

#define T_ROWS 65536
#define CD 128
#define HD 64
#define KSH 512
#define KCO 16
#define RPB 32                 // rows per block
#define NBLK (T_ROWS / RPB)    // 2048

#define LOSS_OFF 8388608ul
#define PS_OFF   8388609ul
#define PC_OFF   8388610ul
#define IDX_OFF  8388611ul
#define US_OFF   8454147ul
#define UC_OFF   8454659ul

#define XP 68                   // padded row stride (floats), odd # of float4
#define GAP 2.5e-4f             // screening margin >> cheap-gumbel error (~4.5e-5)

__device__ int    g_usage_s[KSH];
__device__ int    g_usage_c[KCO];
__device__ int    g_vcount;
__device__ int    g_ticket;
__device__ double g_loss_part[NBLK];

// ---------------- compile-time threefry for the two split keys ----------------
constexpr uint32_t rotl_c(uint32_t x, int d) { return (x << d) | (x >> (32 - d)); }
constexpr uint64_t tf_c(uint32_t k0, uint32_t k1, uint32_t x0, uint32_t x1) {
    uint32_t k2 = k0 ^ k1 ^ 0x1BD11BDAu;
    const int ra[4] = {13, 15, 26, 6};
    const int rb[4] = {17, 29, 16, 24};
    x0 += k0; x1 += k1;
    for (int i = 0; i < 4; i++) { x0 += x1; x1 = rotl_c(x1, ra[i]); x1 ^= x0; }
    x0 += k1; x1 += k2 + 1u;
    for (int i = 0; i < 4; i++) { x0 += x1; x1 = rotl_c(x1, rb[i]); x1 ^= x0; }
    x0 += k2; x1 += k0 + 2u;
    for (int i = 0; i < 4; i++) { x0 += x1; x1 = rotl_c(x1, ra[i]); x1 ^= x0; }
    x0 += k0; x1 += k1 + 3u;
    for (int i = 0; i < 4; i++) { x0 += x1; x1 = rotl_c(x1, rb[i]); x1 ^= x0; }
    x0 += k1; x1 += k2 + 4u;
    for (int i = 0; i < 4; i++) { x0 += x1; x1 = rotl_c(x1, ra[i]); x1 ^= x0; }
    x0 += k2; x1 += k0 + 5u;
    return ((uint64_t)x0 << 32) | x1;
}
constexpr uint64_t KS_P = tf_c(0u, 42u, 0u, 0u);
constexpr uint64_t KC_P = tf_c(0u, 42u, 0u, 1u);
constexpr uint32_t KS0v = (uint32_t)(KS_P >> 32), KS1v = (uint32_t)KS_P;
constexpr uint32_t KC0v = (uint32_t)(KC_P >> 32), KC1v = (uint32_t)KC_P;

// ---------------- packed f32x2 FMA (FFMA2 — PTX-only) ----------------
__device__ __forceinline__ unsigned long long ffma2(unsigned long long a,
                                                    unsigned long long b,
                                                    unsigned long long c) {
    unsigned long long d;
    asm("fma.rn.f32x2 %0, %1, %2, %3;" : "=l"(d) : "l"(a), "l"(b), "l"(c));
    return d;
}
__device__ __forceinline__ float fold2(unsigned long long a) {
    float2 p = *(float2*)&a;
    return __fadd_rn(p.x, p.y);
}

// ---------------- runtime threefry (keys are immediates) ----------------
__device__ __forceinline__ uint32_t rotl32(uint32_t x, int d) {
    return (x << d) | (x >> (32 - d));
}
__device__ __forceinline__ void tf_r(uint32_t& x0, uint32_t& x1, int r) {
    x0 += x1; x1 = rotl32(x1, r); x1 ^= x0;
}
__device__ __forceinline__ uint2 threefry2x32(uint32_t k0, uint32_t k1,
                                              uint32_t x0, uint32_t x1) {
    uint32_t k2 = k0 ^ k1 ^ 0x1BD11BDAu;
    x0 += k0; x1 += k1;
    tf_r(x0,x1,13); tf_r(x0,x1,15); tf_r(x0,x1,26); tf_r(x0,x1,6);
    x0 += k1; x1 += k2 + 1u;
    tf_r(x0,x1,17); tf_r(x0,x1,29); tf_r(x0,x1,16); tf_r(x0,x1,24);
    x0 += k2; x1 += k0 + 2u;
    tf_r(x0,x1,13); tf_r(x0,x1,15); tf_r(x0,x1,26); tf_r(x0,x1,6);
    x0 += k0; x1 += k1 + 3u;
    tf_r(x0,x1,17); tf_r(x0,x1,29); tf_r(x0,x1,16); tf_r(x0,x1,24);
    x0 += k1; x1 += k2 + 4u;
    tf_r(x0,x1,13); tf_r(x0,x1,15); tf_r(x0,x1,26); tf_r(x0,x1,6);
    x0 += k2; x1 += k0 + 5u;
    return make_uint2(x0, x1);
}

__device__ __forceinline__ float uniform_at(uint32_t k0, uint32_t k1, uint32_t idx) {
    uint2 r = threefry2x32(k0, k1, 0u, idx);
    uint32_t bits = r.x ^ r.y;
    const float TINY = 1.17549435e-38f;
    float f = __uint_as_float(0x3F800000u | (bits >> 9)) - 1.0f;
    return fmaxf(TINY, __fadd_rn(f, TINY));
}

__device__ __forceinline__ float gumbel_exact(uint32_t k0, uint32_t k1, uint32_t idx) {
    float u = uniform_at(k0, k1, idx);
    return -logf(-logf(u));
}

// cheap gumbel: |err| <= ~4.5e-5, branchless
__device__ __forceinline__ float gumbel_cheap(uint32_t k0, uint32_t k1, uint32_t idx) {
    float u = uniform_at(k0, k1, idx);
    float inner_m = -0.69314718056f * __log2f(u);
    float s = 1.0f - u;
    float inner_s = s * fmaf(s, fmaf(s, 0.33333333f, 0.5f), 1.0f);
    float inner = (u > 0.99609375f) ? inner_s : inner_m;
    return -0.69314718056f * __log2f(inner);
}

// ---------------- the single fused kernel ----------------
__global__ __launch_bounds__(256, 3) void k_main(const float* __restrict__ x,
                                                 const float* __restrict__ ws,
                                                 const float* __restrict__ wc,
                                                 float* __restrict__ out) {
    extern __shared__ __align__(16) char smem_raw[];
    float* sXs = (float*)smem_raw;            // 32*68
    float* sXc = sXs + RPB * XP;              // 32*68
    float* sW  = sXc + RPB * XP;              // 128*68
    float* sWc = sW  + 128 * XP;              // 16*68
    float* sWW = sWc + 16 * XP;               // 128
    float* sWWc = sWW + 128;                  // 16
    float* sXN = sWWc + 16;                   // 32
    float* sCN = sXN + RPB;                   // 32
    int*   sBG = (int*)(sCN + RPB);           // 32
    int*   sSI = sBG + RPB;                   // 32
    int*   sCI = sSI + RPB;                   // 32
    float* sLossW = (float*)(sCI + RPB);      // 8
    int*   sVC = (int*)(sLossW + 8);          // 1
    int*   sFG = sVC + 1;                     // 1
    int*   sNU = sFG + 1;                     // 1  (count of uncertain rows)
    int*   sUR = sNU + 1;                     // 32 (uncertain row ids)
    float* sRV = (float*)(sUR + RPB);         // 8  (redo reduce staging)
    int*   sRC = (int*)(sRV + 8);             // 8
    float* sMv1 = (float*)(sRC + 8);          // 8*32 per-warp top-1 value
    float* sMv2 = sMv1 + 256;                 // 8*32 per-warp top-2 value
    int*   sMc1 = (int*)(sMv2 + 256);         // 8*32 per-warp top-1 code

    __shared__ double sdd[256];
    __shared__ int isLast;

    int tid = threadIdx.x, lane = tid & 31, w = tid >> 5;
    int cs = lane & 3, rs = lane >> 2;        // code slot (4), row slot (8)
    int ci = tid & 15, ri = tid >> 4;         // color mapping (unchanged)
    int rowbase = blockIdx.x * RPB;

    if (tid == 0) { *sVC = 0; *sFG = 0; *sNU = 0; }

    // load X tile: 32 rows x 128 -> split halves into padded smem
    const float4* gx = (const float4*)(x + (size_t)rowbase * CD);
    #pragma unroll
    for (int i = tid; i < RPB * 32; i += 256) {
        float4 v = gx[i];
        int r = i >> 5, c4 = i & 31;
        if (c4 < 16) ((float4*)(sXs + r * XP))[c4] = v;
        else         ((float4*)(sXc + r * XP))[c4 - 16] = v;
    }
    // color codebook + norms (16 lanes per code row)
    {
        float4 v = ((const float4*)wc)[tid];
        ((float4*)(sWc + (tid >> 4) * XP))[tid & 15] = v;
        float pd = __fadd_rn(__fadd_rn(__fmul_rn(v.x, v.x), __fmul_rn(v.y, v.y)),
                             __fadd_rn(__fmul_rn(v.z, v.z), __fmul_rn(v.w, v.w)));
        #pragma unroll
        for (int o = 8; o > 0; o >>= 1)
            pd = __fadd_rn(pd, __shfl_xor_sync(0xffffffffu, pd, o));
        if ((tid & 15) == 0) sWWc[tid >> 4] = pd;
    }
    __syncthreads();

    // per-row bg + half-norms: warp w -> rows w*4..+3, 8 lanes per row
    {
        int r = w * 4 + (lane >> 3);
        int part = lane & 7;
        float sa = 0.f, ss = 0.f, sc = 0.f;
        #pragma unroll
        for (int j = 0; j < 8; j++) {
            float a = sXs[r * XP + part * 8 + j];
            float b = sXc[r * XP + part * 8 + j];
            sa += fabsf(a) + fabsf(b);
            ss = __fmaf_rn(a, a, ss);
            sc = __fmaf_rn(b, b, sc);
        }
        #pragma unroll
        for (int o = 1; o < 8; o <<= 1) {
            sa += __shfl_xor_sync(0xffffffffu, sa, o);
            ss += __shfl_xor_sync(0xffffffffu, ss, o);
            sc += __shfl_xor_sync(0xffffffffu, sc, o);
        }
        if (part == 0) {
            int b = (sa < 1e-6f);
            sBG[r] = b; sXN[r] = ss; sCN[r] = sc;
            if (!b) *sFG = 1;
        }
    }
    __syncthreads();
    int anyfg = *sFG;

    // slim top-2 screening, 4 rows per thread (rows rs*4+j)
    float v1[4], v2[4];
    int   c1[4];
    #pragma unroll
    for (int j = 0; j < 4; j++) { v1[j] = -INFINITY; v2[j] = -INFINITY; c1[j] = 0x7fffffff; }

#define EVAL_CAND(j_, lg_, code_)                                             \
    {                                                                         \
        float g_ = gumbel_cheap(KS0v, KS1v, rowoff + (uint32_t)(code_));      \
        float v_ = __fadd_rn(lg_, g_);                                        \
        v2[j_] = fmaxf(v2[j_], fminf(v_, v1[j_]));                            \
        if (v_ > v1[j_]) c1[j_] = (code_);                                    \
        v1[j_] = fmaxf(v1[j_], v_);                                           \
    }

    if (anyfg) {
        for (int tile = 0; tile < 4; ++tile) {
            // load W tile + code norms
            const float4* gw = (const float4*)(ws + (size_t)tile * 128 * HD);
            #pragma unroll
            for (int i = tid; i < 128 * 16; i += 256) {
                float4 v = gw[i];
                ((float4*)(sW + (i >> 4) * XP))[i & 15] = v;
                float pd = __fadd_rn(__fadd_rn(__fmul_rn(v.x, v.x), __fmul_rn(v.y, v.y)),
                                     __fadd_rn(__fmul_rn(v.z, v.z), __fmul_rn(v.w, v.w)));
                #pragma unroll
                for (int o = 8; o > 0; o >>= 1)
                    pd = __fadd_rn(pd, __shfl_xor_sync(0xffffffffu, pd, o));
                if ((tid & 15) == 0) sWW[i >> 4] = pd;
            }
            __syncthreads();

            // warp w owns codes tile*128 + 16w + cs + 4k; tile0/warp0 = codes 0..15 (fg-excluded)
            if (tile > 0 || w > 0) {
                unsigned long long acc[4][4];   // [row j][code k]
                #pragma unroll
                for (int j = 0; j < 4; j++)
                    #pragma unroll
                    for (int k = 0; k < 4; k++) acc[j][k] = 0ull;

                const float* wbase = sW + (w * 16 + cs) * XP;
                #pragma unroll
                for (int k4 = 0; k4 < 16; k4++) {
                    ulonglong2 wv[4];
                    #pragma unroll
                    for (int k = 0; k < 4; k++)
                        wv[k] = ((const ulonglong2*)(wbase + 4 * k * XP))[k4];
                    ulonglong2 xv[4];
                    #pragma unroll
                    for (int j = 0; j < 4; j++)
                        xv[j] = ((const ulonglong2*)(sXs + (rs * 4 + j) * XP))[k4];
                    #pragma unroll
                    for (int j = 0; j < 4; j++)
                        #pragma unroll
                        for (int k = 0; k < 4; k++) {
                            acc[j][k] = ffma2(xv[j].x, wv[k].x, acc[j][k]);
                            acc[j][k] = ffma2(xv[j].y, wv[k].y, acc[j][k]);
                        }
                }

                int cbase = tile * 128 + w * 16 + cs;
                #pragma unroll
                for (int j = 0; j < 4; j++) {
                    int r = rs * 4 + j;
                    uint32_t rowoff = (uint32_t)(rowbase + r) << 9;
                    #pragma unroll
                    for (int k = 0; k < 4; k++) {
                        float lg = __fmaf_rn(2.f, fold2(acc[j][k]), -sWW[w * 16 + cs + 4 * k]);
                        EVAL_CAND(j, lg, cbase + 4 * k)
                    }
                }
            }
            __syncthreads();
        }
    } else {
        // pure-bg block: only codes 0..15; x == 0 so logit = -ww; warp 0 evaluates
        {
            float4 v = ((const float4*)ws)[tid];   // first 16 code rows
            float pd = __fadd_rn(__fadd_rn(__fmul_rn(v.x, v.x), __fmul_rn(v.y, v.y)),
                                 __fadd_rn(__fmul_rn(v.z, v.z), __fmul_rn(v.w, v.w)));
            #pragma unroll
            for (int o = 8; o > 0; o >>= 1)
                pd = __fadd_rn(pd, __shfl_xor_sync(0xffffffffu, pd, o));
            if ((tid & 15) == 0) sWW[tid >> 4] = pd;
        }
        __syncthreads();
        if (w == 0) {
            #pragma unroll
            for (int j = 0; j < 4; j++) {
                int r = rs * 4 + j;
                uint32_t rowoff = (uint32_t)(rowbase + r) << 9;
                #pragma unroll
                for (int k = 0; k < 4; k++) {
                    float lg = -sWW[cs + 4 * k];
                    EVAL_CAND(j, lg, cs + 4 * k)
                }
            }
        }
    }

    // ---- color: exact path, 16 codes (mapping unchanged) ----
    float cbest[2]; int cbidx[2];
    #pragma unroll
    for (int q = 0; q < 2; q++) {
        int r = 16 * q + ri;
        unsigned long long a2 = 0ull;
        #pragma unroll
        for (int k4 = 0; k4 < 16; k4++) {
            ulonglong2 xv = ((const ulonglong2*)(sXc + r * XP))[k4];
            ulonglong2 wv = ((const ulonglong2*)(sWc + ci * XP))[k4];
            a2 = ffma2(xv.x, wv.x, a2);
            a2 = ffma2(xv.y, wv.y, a2);
        }
        float a = fold2(a2);
        float g = gumbel_exact(KC0v, KC1v, ((uint32_t)(rowbase + r) << 4) + (uint32_t)ci);
        float d = __fadd_rn(__fadd_rn(sCN[r], sWWc[ci]), -__fmul_rn(2.f, a));
        cbest[q] = __fadd_rn(-d, g);
        cbidx[q] = ci;
    }
    #pragma unroll
    for (int o = 8; o > 0; o >>= 1) {
        #pragma unroll
        for (int q = 0; q < 2; q++) {
            float cv = __shfl_xor_sync(0xffffffffu, cbest[q], o);
            int   cb = __shfl_xor_sync(0xffffffffu, cbidx[q], o);
            if (cv > cbest[q] || (cv == cbest[q] && cb < cbidx[q])) { cbest[q] = cv; cbidx[q] = cb; }
        }
    }
    if ((lane & 15) == 0) {
        #pragma unroll
        for (int q = 0; q < 2; q++) sCI[16 * q + ri] = cbidx[q];
    }

    // ---- shape: merge across the 4 cs lanes (same rows), write per-warp table ----
    #pragma unroll
    for (int o = 1; o < 4; o <<= 1) {
        #pragma unroll
        for (int j = 0; j < 4; j++) {
            float ov1 = __shfl_xor_sync(0xffffffffu, v1[j], o);
            int   oc1 = __shfl_xor_sync(0xffffffffu, c1[j], o);
            float ov2 = __shfl_xor_sync(0xffffffffu, v2[j], o);
            bool takeO = (ov1 > v1[j]) || (ov1 == v1[j] && oc1 < c1[j]);
            v2[j] = fmaxf(fmaxf(v2[j], ov2), fminf(v1[j], ov1));
            if (takeO) c1[j] = oc1;
            v1[j] = fmaxf(v1[j], ov1);
        }
    }
    if (cs == 0) {
        #pragma unroll
        for (int j = 0; j < 4; j++) {
            int idx = w * 32 + rs * 4 + j;
            sMv1[idx] = v1[j]; sMv2[idx] = v2[j]; sMc1[idx] = c1[j];
        }
    }
    __syncthreads();

    // ---- cross-warp merge: thread r<32 folds the 8 per-warp top-2 entries ----
    if (tid < 32) {
        int r = tid;
        float V1 = -INFINITY, V2 = -INFINITY; int C1 = 0x7fffffff;
        #pragma unroll
        for (int wi = 0; wi < 8; wi++) {
            float a1 = sMv1[wi * 32 + r];
            float a2 = sMv2[wi * 32 + r];
            int   ac = sMc1[wi * 32 + r];
            bool takeO = (a1 > V1) || (a1 == V1 && ac < C1);
            V2 = fmaxf(fmaxf(V2, a2), fminf(V1, a1));
            if (takeO) C1 = ac;
            V1 = fmaxf(V1, a1);
        }
        bool unc = !(V1 - V2 > GAP) || (sBG[r] && anyfg);
        if (unc) {
            int p = atomicAdd(sNU, 1);
            sUR[p] = r;
        } else {
            sSI[r] = C1;
        }
    }
    __syncthreads();

    // ---- block-cooperative exact redo of uncertain rows (rare) ----
    int nu = *sNU;
    for (int u = 0; u < nu; u++) {
        int r = sUR[u];
        int bg = sBG[r];
        int lo = bg ? 0 : KCO;
        int hi = bg ? KCO : KSH;
        const float* xrow = sXs + r * XP;
        float xs = sXN[r];
        uint32_t rowoff = (uint32_t)(rowbase + r) << 9;
        float bv = -INFINITY; int bc = 0x7fffffff;
        for (int c = lo + tid; c < hi; c += 256) {
            const float* wr = ws + c * HD;
            float dot = 0.f, ww = 0.f;
            #pragma unroll
            for (int j = 0; j < HD; j++) {
                float wv = wr[j];
                dot = __fmaf_rn(xrow[j], wv, dot);
                ww  = __fmaf_rn(wv, wv, ww);
            }
            float d = __fadd_rn(__fadd_rn(xs, ww), -__fmul_rn(2.f, dot));
            float g = gumbel_exact(KS0v, KS1v, rowoff + (uint32_t)c);
            float v = __fadd_rn(-d, g);
            if (v > bv || (v == bv && c < bc)) { bv = v; bc = c; }
        }
        #pragma unroll
        for (int o = 16; o > 0; o >>= 1) {
            float ov = __shfl_xor_sync(0xffffffffu, bv, o);
            int   oc = __shfl_xor_sync(0xffffffffu, bc, o);
            if (ov > bv || (ov == bv && oc < bc)) { bv = ov; bc = oc; }
        }
        if (lane == 0) { sRV[w] = bv; sRC[w] = bc; }
        __syncthreads();
        if (tid == 0) {
            float fv = sRV[0]; int fc = sRC[0];
            #pragma unroll
            for (int i = 1; i < 8; i++)
                if (sRV[i] > fv || (sRV[i] == fv && sRC[i] < fc)) { fv = sRV[i]; fc = sRC[i]; }
            sSI[r] = fc;
        }
        __syncthreads();
    }

    // ---- outputs: quantized rows, idx, usage, loss ----
    float eacc = 0.f; int vcnt = 0;
    for (int t = 0; t < 4; t++) {
        int r = w * 4 + t;
        int widx = sSI[r], cidx = sCI[r];
        size_t grow = (size_t)rowbase + r;
        float4 wv, xv;
        if (lane < 16) {
            wv = ((const float4*)(ws + widx * HD))[lane];
            xv = ((const float4*)(sXs + r * XP))[lane];
        } else {
            wv = ((const float4*)(wc + cidx * HD))[lane - 16];
            xv = ((const float4*)(sXc + r * XP))[lane - 16];
        }
        ((float4*)out)[grow * 32 + lane] = wv;
        float dx = wv.x - xv.x, dy = wv.y - xv.y, dz = wv.z - xv.z, dw = wv.w - xv.w;
        float e = dx * dx + dy * dy + dz * dz + dw * dw;
        #pragma unroll
        for (int o = 16; o > 0; o >>= 1)
            e += __shfl_xor_sync(0xffffffffu, e, o);
        if (lane == 0) {
            out[IDX_OFF + grow] = (float)widx;
            if (!sBG[r]) {
                atomicAdd(&g_usage_s[widx], 1);
                atomicAdd(&g_usage_c[cidx], 1);
                vcnt++;
                eacc += e;
            }
        }
    }
    if (lane == 0) {
        sLossW[w] = eacc;
        atomicAdd(sVC, vcnt);
    }
    __syncthreads();
    if (tid == 0) {
        double L = 0.0;
        #pragma unroll
        for (int i = 0; i < 8; i++) L += (double)sLossW[i];
        g_loss_part[blockIdx.x] = L;
        atomicAdd(&g_vcount, *sVC);
    }

    // ---- last block finalizes + resets accumulators (graph-replay safe) ----
    __threadfence();
    if (tid == 0) {
        int t = atomicAdd(&g_ticket, 1);
        isLast = (t == NBLK - 1);
    }
    __syncthreads();
    if (!isLast) return;
    __threadfence();

    double a = 0.0;
    for (int i = tid; i < NBLK; i += 256) a += g_loss_part[i];
    sdd[tid] = a; __syncthreads();
    for (int s = 128; s > 0; s >>= 1) { if (tid < s) sdd[tid] += sdd[tid + s]; __syncthreads(); }
    double vc = (double)g_vcount;
    if (tid == 0) out[LOSS_OFF] = (float)(1.25 * sdd[0] / (vc * 128.0));
    __syncthreads();

    double e = 0.0;
    for (int i = tid; i < KSH; i += 256) {
        double p = (double)g_usage_s[i] / vc;
        e += p * log(p + 1e-10);
        out[US_OFF + i] = (float)g_usage_s[i];
    }
    sdd[tid] = e; __syncthreads();
    for (int s = 128; s > 0; s >>= 1) { if (tid < s) sdd[tid] += sdd[tid + s]; __syncthreads(); }
    if (tid == 0) out[PS_OFF] = (float)exp(-sdd[0]);
    __syncthreads();

    double ec = 0.0;
    if (tid < KCO) {
        double p = (double)g_usage_c[tid] / vc;
        ec = p * log(p + 1e-10);
        out[UC_OFF + tid] = (float)g_usage_c[tid];
    }
    sdd[tid] = ec; __syncthreads();
    for (int s = 128; s > 0; s >>= 1) { if (tid < s) sdd[tid] += sdd[tid + s]; __syncthreads(); }
    if (tid == 0) out[PC_OFF] = (float)exp(-sdd[0]);
    __syncthreads();

    for (int i = tid; i < KSH; i += 256) g_usage_s[i] = 0;
    if (tid < KCO) g_usage_c[tid] = 0;
    if (tid == 0) { g_vcount = 0; g_ticket = 0; }
}

#define SMEM_BYTES ((RPB*XP*2 + 128*XP + 16*XP + 128 + 16 + RPB + RPB) * 4 \
                    + (RPB + RPB + RPB + 8 + 1 + 1) * 4 + (1 + RPB + 8 + 8) * 4 \
                    + (256 + 256 + 256) * 4 + 64)

extern "C" void kernel_launch(void* const* d_in, const int* in_sizes, int n_in,
                              void* d_out, int out_size) {
    const float* x  = (const float*)d_in[0];   // inputs [16,4096,128]
    const float* ws = (const float*)d_in[2];   // w_shape [512,64]
    const float* wc = (const float*)d_in[3];   // w_color [16,64]
    float* out = (float*)d_out;
    cudaFuncSetAttribute(k_main, cudaFuncAttributeMaxDynamicSharedMemorySize, SMEM_BYTES);
    k_main<<<NBLK, 256, SMEM_BYTES>>>(x, ws, wc, out);
}

// round 12
// speedup vs baseline: 1.0027x; 1.0027x over previous
#include <cuda_runtime.h>
#include <stdint.h>
#include <math.h>

#define T_ROWS 65536
#define CD 128
#define HD 64
#define KSH 512
#define KCO 16
#define RPB 32                 // rows per block
#define NBLK (T_ROWS / RPB)    // 2048

#define LOSS_OFF 8388608ul
#define PS_OFF   8388609ul
#define PC_OFF   8388610ul
#define IDX_OFF  8388611ul
#define US_OFF   8454147ul
#define UC_OFF   8454659ul

#define XP 68                   // padded row stride (floats), odd # of float4
#define GAP 2.5e-4f             // screening margin >> cheap-gumbel error (~4.5e-5)

__device__ int    g_usage_s[KSH];
__device__ int    g_usage_c[KCO];
__device__ int    g_vcount;
__device__ int    g_ticket;
__device__ double g_loss_part[NBLK];

// ---------------- compile-time threefry for the two split keys ----------------
constexpr uint32_t rotl_c(uint32_t x, int d) { return (x << d) | (x >> (32 - d)); }
constexpr uint64_t tf_c(uint32_t k0, uint32_t k1, uint32_t x0, uint32_t x1) {
    uint32_t k2 = k0 ^ k1 ^ 0x1BD11BDAu;
    const int ra[4] = {13, 15, 26, 6};
    const int rb[4] = {17, 29, 16, 24};
    x0 += k0; x1 += k1;
    for (int i = 0; i < 4; i++) { x0 += x1; x1 = rotl_c(x1, ra[i]); x1 ^= x0; }
    x0 += k1; x1 += k2 + 1u;
    for (int i = 0; i < 4; i++) { x0 += x1; x1 = rotl_c(x1, rb[i]); x1 ^= x0; }
    x0 += k2; x1 += k0 + 2u;
    for (int i = 0; i < 4; i++) { x0 += x1; x1 = rotl_c(x1, ra[i]); x1 ^= x0; }
    x0 += k0; x1 += k1 + 3u;
    for (int i = 0; i < 4; i++) { x0 += x1; x1 = rotl_c(x1, rb[i]); x1 ^= x0; }
    x0 += k1; x1 += k2 + 4u;
    for (int i = 0; i < 4; i++) { x0 += x1; x1 = rotl_c(x1, ra[i]); x1 ^= x0; }
    x0 += k2; x1 += k0 + 5u;
    return ((uint64_t)x0 << 32) | x1;
}
constexpr uint64_t KS_P = tf_c(0u, 42u, 0u, 0u);
constexpr uint64_t KC_P = tf_c(0u, 42u, 0u, 1u);
constexpr uint32_t KS0v = (uint32_t)(KS_P >> 32), KS1v = (uint32_t)KS_P;
constexpr uint32_t KC0v = (uint32_t)(KC_P >> 32), KC1v = (uint32_t)KC_P;

// ---------------- packed f32x2 FMA (FFMA2 — PTX-only) ----------------
__device__ __forceinline__ unsigned long long ffma2(unsigned long long a,
                                                    unsigned long long b,
                                                    unsigned long long c) {
    unsigned long long d;
    asm("fma.rn.f32x2 %0, %1, %2, %3;" : "=l"(d) : "l"(a), "l"(b), "l"(c));
    return d;
}
__device__ __forceinline__ float fold2(unsigned long long a) {
    float2 p = *(float2*)&a;
    return __fadd_rn(p.x, p.y);
}

// ---------------- runtime threefry (keys are immediates) ----------------
__device__ __forceinline__ uint32_t rotl32(uint32_t x, int d) {
    return (x << d) | (x >> (32 - d));
}
__device__ __forceinline__ void tf_r(uint32_t& x0, uint32_t& x1, int r) {
    x0 += x1; x1 = rotl32(x1, r); x1 ^= x0;
}
__device__ __forceinline__ uint2 threefry2x32(uint32_t k0, uint32_t k1,
                                              uint32_t x0, uint32_t x1) {
    uint32_t k2 = k0 ^ k1 ^ 0x1BD11BDAu;
    x0 += k0; x1 += k1;
    tf_r(x0,x1,13); tf_r(x0,x1,15); tf_r(x0,x1,26); tf_r(x0,x1,6);
    x0 += k1; x1 += k2 + 1u;
    tf_r(x0,x1,17); tf_r(x0,x1,29); tf_r(x0,x1,16); tf_r(x0,x1,24);
    x0 += k2; x1 += k0 + 2u;
    tf_r(x0,x1,13); tf_r(x0,x1,15); tf_r(x0,x1,26); tf_r(x0,x1,6);
    x0 += k0; x1 += k1 + 3u;
    tf_r(x0,x1,17); tf_r(x0,x1,29); tf_r(x0,x1,16); tf_r(x0,x1,24);
    x0 += k1; x1 += k2 + 4u;
    tf_r(x0,x1,13); tf_r(x0,x1,15); tf_r(x0,x1,26); tf_r(x0,x1,6);
    x0 += k2; x1 += k0 + 5u;
    return make_uint2(x0, x1);
}

__device__ __forceinline__ float uniform_at(uint32_t k0, uint32_t k1, uint32_t idx) {
    uint2 r = threefry2x32(k0, k1, 0u, idx);
    uint32_t bits = r.x ^ r.y;
    const float TINY = 1.17549435e-38f;
    float f = __uint_as_float(0x3F800000u | (bits >> 9)) - 1.0f;
    return fmaxf(TINY, __fadd_rn(f, TINY));
}

__device__ __forceinline__ float gumbel_exact(uint32_t k0, uint32_t k1, uint32_t idx) {
    float u = uniform_at(k0, k1, idx);
    return -logf(-logf(u));
}

// cheap gumbel: |err| <= ~4.5e-5, branchless
__device__ __forceinline__ float gumbel_cheap(uint32_t k0, uint32_t k1, uint32_t idx) {
    float u = uniform_at(k0, k1, idx);
    float inner_m = -0.69314718056f * __log2f(u);
    float s = 1.0f - u;
    float inner_s = s * fmaf(s, fmaf(s, 0.33333333f, 0.5f), 1.0f);
    float inner = (u > 0.99609375f) ? inner_s : inner_m;
    return -0.69314718056f * __log2f(inner);
}

// ---------------- the single fused kernel ----------------
__global__ __launch_bounds__(256, 3) void k_main(const float* __restrict__ x,
                                                 const float* __restrict__ ws,
                                                 const float* __restrict__ wc,
                                                 float* __restrict__ out) {
    extern __shared__ __align__(16) char smem_raw[];
    float* sXs = (float*)smem_raw;            // 32*68
    float* sXc = sXs + RPB * XP;              // 32*68
    float* sW  = sXc + RPB * XP;              // 128*68
    float* sWc = sW  + 128 * XP;              // 16*68
    float* sWW = sWc + 16 * XP;               // 128
    float* sWWc = sWW + 128;                  // 16
    float* sXN = sWWc + 16;                   // 32
    float* sCN = sXN + RPB;                   // 32
    int*   sBG = (int*)(sCN + RPB);           // 32
    int*   sSI = sBG + RPB;                   // 32
    int*   sCI = sSI + RPB;                   // 32
    float* sLossW = (float*)(sCI + RPB);      // 8
    int*   sVC = (int*)(sLossW + 8);          // 1
    int*   sFG = sVC + 1;                     // 1
    int*   sNU = sFG + 1;                     // 1  (count of uncertain rows)
    int*   sUR = sNU + 1;                     // 32 (uncertain row ids)
    float* sRV = (float*)(sUR + RPB);         // 8  (redo reduce staging)
    int*   sRC = (int*)(sRV + 8);             // 8
    float* sMv1 = (float*)(sRC + 8);          // 8*32 per-warp top-1 value
    float* sMv2 = sMv1 + 256;                 // 8*32 per-warp top-2 value
    int*   sMc1 = (int*)(sMv2 + 256);         // 8*32 per-warp top-1 code

    __shared__ double sdd[256];
    __shared__ int isLast;

    int tid = threadIdx.x, lane = tid & 31, w = tid >> 5;
    int cs = lane & 3, rs = lane >> 2;        // code slot (4), row slot (8)
    int ci = tid & 15, ri = tid >> 4;         // color mapping (unchanged)
    int rowbase = blockIdx.x * RPB;

    if (tid == 0) { *sVC = 0; *sFG = 0; *sNU = 0; }

    // load X tile: 32 rows x 128 -> split halves into padded smem
    const float4* gx = (const float4*)(x + (size_t)rowbase * CD);
    #pragma unroll
    for (int i = tid; i < RPB * 32; i += 256) {
        float4 v = gx[i];
        int r = i >> 5, c4 = i & 31;
        if (c4 < 16) ((float4*)(sXs + r * XP))[c4] = v;
        else         ((float4*)(sXc + r * XP))[c4 - 16] = v;
    }
    // color codebook + norms (16 lanes per code row)
    {
        float4 v = ((const float4*)wc)[tid];
        ((float4*)(sWc + (tid >> 4) * XP))[tid & 15] = v;
        float pd = __fadd_rn(__fadd_rn(__fmul_rn(v.x, v.x), __fmul_rn(v.y, v.y)),
                             __fadd_rn(__fmul_rn(v.z, v.z), __fmul_rn(v.w, v.w)));
        #pragma unroll
        for (int o = 8; o > 0; o >>= 1)
            pd = __fadd_rn(pd, __shfl_xor_sync(0xffffffffu, pd, o));
        if ((tid & 15) == 0) sWWc[tid >> 4] = pd;
    }
    __syncthreads();

    // per-row bg + half-norms: warp w -> rows w*4..+3, 8 lanes per row
    {
        int r = w * 4 + (lane >> 3);
        int part = lane & 7;
        float sa = 0.f, ss = 0.f, sc = 0.f;
        #pragma unroll
        for (int j = 0; j < 8; j++) {
            float a = sXs[r * XP + part * 8 + j];
            float b = sXc[r * XP + part * 8 + j];
            sa += fabsf(a) + fabsf(b);
            ss = __fmaf_rn(a, a, ss);
            sc = __fmaf_rn(b, b, sc);
        }
        #pragma unroll
        for (int o = 1; o < 8; o <<= 1) {
            sa += __shfl_xor_sync(0xffffffffu, sa, o);
            ss += __shfl_xor_sync(0xffffffffu, ss, o);
            sc += __shfl_xor_sync(0xffffffffu, sc, o);
        }
        if (part == 0) {
            int b = (sa < 1e-6f);
            sBG[r] = b; sXN[r] = ss; sCN[r] = sc;
            if (!b) *sFG = 1;
        }
    }
    __syncthreads();
    int anyfg = *sFG;

    // slim top-2 screening, 4 rows per thread (rows rs*4+j)
    float v1[4], v2[4];
    int   c1[4];
    #pragma unroll
    for (int j = 0; j < 4; j++) { v1[j] = -INFINITY; v2[j] = -INFINITY; c1[j] = 0x7fffffff; }

#define EVAL_CAND(j_, lg_, code_)                                             \
    {                                                                         \
        float g_ = gumbel_cheap(KS0v, KS1v, rowoff + (uint32_t)(code_));      \
        float v_ = __fadd_rn(lg_, g_);                                        \
        v2[j_] = fmaxf(v2[j_], fminf(v_, v1[j_]));                            \
        if (v_ > v1[j_]) c1[j_] = (code_);                                    \
        v1[j_] = fmaxf(v1[j_], v_);                                           \
    }

    if (anyfg) {
        for (int tile = 0; tile < 4; ++tile) {
            // load W tile + code norms
            const float4* gw = (const float4*)(ws + (size_t)tile * 128 * HD);
            #pragma unroll
            for (int i = tid; i < 128 * 16; i += 256) {
                float4 v = gw[i];
                ((float4*)(sW + (i >> 4) * XP))[i & 15] = v;
                float pd = __fadd_rn(__fadd_rn(__fmul_rn(v.x, v.x), __fmul_rn(v.y, v.y)),
                                     __fadd_rn(__fmul_rn(v.z, v.z), __fmul_rn(v.w, v.w)));
                #pragma unroll
                for (int o = 8; o > 0; o >>= 1)
                    pd = __fadd_rn(pd, __shfl_xor_sync(0xffffffffu, pd, o));
                if ((tid & 15) == 0) sWW[i >> 4] = pd;
            }
            __syncthreads();

            // warp w owns codes tile*128 + 16w + cs + 4k; tile0/warp0 = codes 0..15 (fg-excluded)
            if (tile > 0 || w > 0) {
                unsigned long long acc[4][4];   // [row j][code k]
                #pragma unroll
                for (int j = 0; j < 4; j++)
                    #pragma unroll
                    for (int k = 0; k < 4; k++) acc[j][k] = 0ull;

                const float* wbase = sW + (w * 16 + cs) * XP;
                #pragma unroll
                for (int k4 = 0; k4 < 16; k4++) {
                    ulonglong2 wv[4];
                    #pragma unroll
                    for (int k = 0; k < 4; k++)
                        wv[k] = ((const ulonglong2*)(wbase + 4 * k * XP))[k4];
                    ulonglong2 xv[4];
                    #pragma unroll
                    for (int j = 0; j < 4; j++)
                        xv[j] = ((const ulonglong2*)(sXs + (rs * 4 + j) * XP))[k4];
                    #pragma unroll
                    for (int j = 0; j < 4; j++)
                        #pragma unroll
                        for (int k = 0; k < 4; k++) {
                            acc[j][k] = ffma2(xv[j].x, wv[k].x, acc[j][k]);
                            acc[j][k] = ffma2(xv[j].y, wv[k].y, acc[j][k]);
                        }
                }

                int cbase = tile * 128 + w * 16 + cs;
                #pragma unroll
                for (int j = 0; j < 4; j++) {
                    int r = rs * 4 + j;
                    uint32_t rowoff = (uint32_t)(rowbase + r) << 9;
                    #pragma unroll
                    for (int k = 0; k < 4; k++) {
                        float lg = __fmaf_rn(2.f, fold2(acc[j][k]), -sWW[w * 16 + cs + 4 * k]);
                        EVAL_CAND(j, lg, cbase + 4 * k)
                    }
                }
            }
            __syncthreads();
        }
    } else {
        // pure-bg block: only codes 0..15; x == 0 so logit = -ww; warp 0 evaluates
        {
            float4 v = ((const float4*)ws)[tid];   // first 16 code rows
            float pd = __fadd_rn(__fadd_rn(__fmul_rn(v.x, v.x), __fmul_rn(v.y, v.y)),
                                 __fadd_rn(__fmul_rn(v.z, v.z), __fmul_rn(v.w, v.w)));
            #pragma unroll
            for (int o = 8; o > 0; o >>= 1)
                pd = __fadd_rn(pd, __shfl_xor_sync(0xffffffffu, pd, o));
            if ((tid & 15) == 0) sWW[tid >> 4] = pd;
        }
        __syncthreads();
        if (w == 0) {
            #pragma unroll
            for (int j = 0; j < 4; j++) {
                int r = rs * 4 + j;
                uint32_t rowoff = (uint32_t)(rowbase + r) << 9;
                #pragma unroll
                for (int k = 0; k < 4; k++) {
                    float lg = -sWW[cs + 4 * k];
                    EVAL_CAND(j, lg, cs + 4 * k)
                }
            }
        }
    }

    // ---- color: exact path, 16 codes (mapping unchanged) ----
    float cbest[2]; int cbidx[2];
    #pragma unroll
    for (int q = 0; q < 2; q++) {
        int r = 16 * q + ri;
        unsigned long long a2 = 0ull;
        #pragma unroll
        for (int k4 = 0; k4 < 16; k4++) {
            ulonglong2 xv = ((const ulonglong2*)(sXc + r * XP))[k4];
            ulonglong2 wv = ((const ulonglong2*)(sWc + ci * XP))[k4];
            a2 = ffma2(xv.x, wv.x, a2);
            a2 = ffma2(xv.y, wv.y, a2);
        }
        float a = fold2(a2);
        float g = gumbel_exact(KC0v, KC1v, ((uint32_t)(rowbase + r) << 4) + (uint32_t)ci);
        float d = __fadd_rn(__fadd_rn(sCN[r], sWWc[ci]), -__fmul_rn(2.f, a));
        cbest[q] = __fadd_rn(-d, g);
        cbidx[q] = ci;
    }
    #pragma unroll
    for (int o = 8; o > 0; o >>= 1) {
        #pragma unroll
        for (int q = 0; q < 2; q++) {
            float cv = __shfl_xor_sync(0xffffffffu, cbest[q], o);
            int   cb = __shfl_xor_sync(0xffffffffu, cbidx[q], o);
            if (cv > cbest[q] || (cv == cbest[q] && cb < cbidx[q])) { cbest[q] = cv; cbidx[q] = cb; }
        }
    }
    if ((lane & 15) == 0) {
        #pragma unroll
        for (int q = 0; q < 2; q++) sCI[16 * q + ri] = cbidx[q];
    }

    // ---- shape: merge across the 4 cs lanes (same rows), write per-warp table ----
    #pragma unroll
    for (int o = 1; o < 4; o <<= 1) {
        #pragma unroll
        for (int j = 0; j < 4; j++) {
            float ov1 = __shfl_xor_sync(0xffffffffu, v1[j], o);
            int   oc1 = __shfl_xor_sync(0xffffffffu, c1[j], o);
            float ov2 = __shfl_xor_sync(0xffffffffu, v2[j], o);
            bool takeO = (ov1 > v1[j]) || (ov1 == v1[j] && oc1 < c1[j]);
            v2[j] = fmaxf(fmaxf(v2[j], ov2), fminf(v1[j], ov1));
            if (takeO) c1[j] = oc1;
            v1[j] = fmaxf(v1[j], ov1);
        }
    }
    if (cs == 0) {
        #pragma unroll
        for (int j = 0; j < 4; j++) {
            int idx = w * 32 + rs * 4 + j;
            sMv1[idx] = v1[j]; sMv2[idx] = v2[j]; sMc1[idx] = c1[j];
        }
    }
    __syncthreads();

    // ---- cross-warp merge: thread r<32 folds the 8 per-warp top-2 entries ----
    if (tid < 32) {
        int r = tid;
        float V1 = -INFINITY, V2 = -INFINITY; int C1 = 0x7fffffff;
        #pragma unroll
        for (int wi = 0; wi < 8; wi++) {
            float a1 = sMv1[wi * 32 + r];
            float a2 = sMv2[wi * 32 + r];
            int   ac = sMc1[wi * 32 + r];
            bool takeO = (a1 > V1) || (a1 == V1 && ac < C1);
            V2 = fmaxf(fmaxf(V2, a2), fminf(V1, a1));
            if (takeO) C1 = ac;
            V1 = fmaxf(V1, a1);
        }
        bool unc = !(V1 - V2 > GAP) || (sBG[r] && anyfg);
        if (unc) {
            int p = atomicAdd(sNU, 1);
            sUR[p] = r;
        } else {
            sSI[r] = C1;
        }
    }
    __syncthreads();

    // ---- block-cooperative exact redo of uncertain rows (rare) ----
    int nu = *sNU;
    for (int u = 0; u < nu; u++) {
        int r = sUR[u];
        int bg = sBG[r];
        int lo = bg ? 0 : KCO;
        int hi = bg ? KCO : KSH;
        const float* xrow = sXs + r * XP;
        float xs = sXN[r];
        uint32_t rowoff = (uint32_t)(rowbase + r) << 9;
        float bv = -INFINITY; int bc = 0x7fffffff;
        for (int c = lo + tid; c < hi; c += 256) {
            const float* wr = ws + c * HD;
            float dot = 0.f, ww = 0.f;
            #pragma unroll
            for (int j = 0; j < HD; j++) {
                float wv = wr[j];
                dot = __fmaf_rn(xrow[j], wv, dot);
                ww  = __fmaf_rn(wv, wv, ww);
            }
            float d = __fadd_rn(__fadd_rn(xs, ww), -__fmul_rn(2.f, dot));
            float g = gumbel_exact(KS0v, KS1v, rowoff + (uint32_t)c);
            float v = __fadd_rn(-d, g);
            if (v > bv || (v == bv && c < bc)) { bv = v; bc = c; }
        }
        #pragma unroll
        for (int o = 16; o > 0; o >>= 1) {
            float ov = __shfl_xor_sync(0xffffffffu, bv, o);
            int   oc = __shfl_xor_sync(0xffffffffu, bc, o);
            if (ov > bv || (ov == bv && oc < bc)) { bv = ov; bc = oc; }
        }
        if (lane == 0) { sRV[w] = bv; sRC[w] = bc; }
        __syncthreads();
        if (tid == 0) {
            float fv = sRV[0]; int fc = sRC[0];
            #pragma unroll
            for (int i = 1; i < 8; i++)
                if (sRV[i] > fv || (sRV[i] == fv && sRC[i] < fc)) { fv = sRV[i]; fc = sRC[i]; }
            sSI[r] = fc;
        }
        __syncthreads();
    }

    // ---- outputs: quantized rows, idx, usage, loss ----
    float eacc = 0.f; int vcnt = 0;
    for (int t = 0; t < 4; t++) {
        int r = w * 4 + t;
        int widx = sSI[r], cidx = sCI[r];
        size_t grow = (size_t)rowbase + r;
        float4 wv, xv;
        if (lane < 16) {
            wv = ((const float4*)(ws + widx * HD))[lane];
            xv = ((const float4*)(sXs + r * XP))[lane];
        } else {
            wv = ((const float4*)(wc + cidx * HD))[lane - 16];
            xv = ((const float4*)(sXc + r * XP))[lane - 16];
        }
        ((float4*)out)[grow * 32 + lane] = wv;
        float dx = wv.x - xv.x, dy = wv.y - xv.y, dz = wv.z - xv.z, dw = wv.w - xv.w;
        float e = dx * dx + dy * dy + dz * dz + dw * dw;
        #pragma unroll
        for (int o = 16; o > 0; o >>= 1)
            e += __shfl_xor_sync(0xffffffffu, e, o);
        if (lane == 0) {
            out[IDX_OFF + grow] = (float)widx;
            if (!sBG[r]) {
                atomicAdd(&g_usage_s[widx], 1);
                atomicAdd(&g_usage_c[cidx], 1);
                vcnt++;
                eacc += e;
            }
        }
    }
    if (lane == 0) {
        sLossW[w] = eacc;
        atomicAdd(sVC, vcnt);
    }
    __syncthreads();
    if (tid == 0) {
        double L = 0.0;
        #pragma unroll
        for (int i = 0; i < 8; i++) L += (double)sLossW[i];
        g_loss_part[blockIdx.x] = L;
        atomicAdd(&g_vcount, *sVC);
    }

    // ---- last block finalizes + resets accumulators (graph-replay safe) ----
    __threadfence();
    if (tid == 0) {
        int t = atomicAdd(&g_ticket, 1);
        isLast = (t == NBLK - 1);
    }
    __syncthreads();
    if (!isLast) return;
    __threadfence();

    double a = 0.0;
    for (int i = tid; i < NBLK; i += 256) a += g_loss_part[i];
    sdd[tid] = a; __syncthreads();
    for (int s = 128; s > 0; s >>= 1) { if (tid < s) sdd[tid] += sdd[tid + s]; __syncthreads(); }
    double vc = (double)g_vcount;
    if (tid == 0) out[LOSS_OFF] = (float)(1.25 * sdd[0] / (vc * 128.0));
    __syncthreads();

    double e = 0.0;
    for (int i = tid; i < KSH; i += 256) {
        double p = (double)g_usage_s[i] / vc;
        e += p * log(p + 1e-10);
        out[US_OFF + i] = (float)g_usage_s[i];
    }
    sdd[tid] = e; __syncthreads();
    for (int s = 128; s > 0; s >>= 1) { if (tid < s) sdd[tid] += sdd[tid + s]; __syncthreads(); }
    if (tid == 0) out[PS_OFF] = (float)exp(-sdd[0]);
    __syncthreads();

    double ec = 0.0;
    if (tid < KCO) {
        double p = (double)g_usage_c[tid] / vc;
        ec = p * log(p + 1e-10);
        out[UC_OFF + tid] = (float)g_usage_c[tid];
    }
    sdd[tid] = ec; __syncthreads();
    for (int s = 128; s > 0; s >>= 1) { if (tid < s) sdd[tid] += sdd[tid + s]; __syncthreads(); }
    if (tid == 0) out[PC_OFF] = (float)exp(-sdd[0]);
    __syncthreads();

    for (int i = tid; i < KSH; i += 256) g_usage_s[i] = 0;
    if (tid < KCO) g_usage_c[tid] = 0;
    if (tid == 0) { g_vcount = 0; g_ticket = 0; }
}

#define SMEM_BYTES ((RPB*XP*2 + 128*XP + 16*XP + 128 + 16 + RPB + RPB) * 4 \
                    + (RPB + RPB + RPB + 8 + 1 + 1) * 4 + (1 + RPB + 8 + 8) * 4 \
                    + (256 + 256 + 256) * 4 + 64)

extern "C" void kernel_launch(void* const* d_in, const int* in_sizes, int n_in,
                              void* d_out, int out_size) {
    const float* x  = (const float*)d_in[0];   // inputs [16,4096,128]
    const float* ws = (const float*)d_in[2];   // w_shape [512,64]
    const float* wc = (const float*)d_in[3];   // w_color [16,64]
    float* out = (float*)d_out;
    cudaFuncSetAttribute(k_main, cudaFuncAttributeMaxDynamicSharedMemorySize, SMEM_BYTES);
    k_main<<<NBLK, 256, SMEM_BYTES>>>(x, ws, wc, out);
}

// round 14
// speedup vs baseline: 1.2981x; 1.2946x over previous
#include <cuda_runtime.h>
#include <stdint.h>
#include <math.h>

#define T_ROWS 65536
#define CD 128
#define HD 64
#define KSH 512
#define KCO 16
#define RPB 32
#define NBLK (T_ROWS / RPB)

#define LOSS_OFF 8388608ul
#define PS_OFF   8388609ul
#define PC_OFF   8388610ul
#define IDX_OFF  8388611ul
#define US_OFF   8454147ul
#define UC_OFF   8454659ul

#define XP 68
#define GAPT 1.0e-3f

__device__ int    g_usage_s[KSH];
__device__ int    g_usage_c[KCO];
__device__ int    g_vcount;
__device__ int    g_ticket;
__device__ double g_loss_part[NBLK];

constexpr uint32_t rotl_c(uint32_t x, int d) { return (x << d) | (x >> (32 - d)); }
constexpr uint64_t tf_c(uint32_t k0, uint32_t k1, uint32_t x0, uint32_t x1) {
    uint32_t k2 = k0 ^ k1 ^ 0x1BD11BDAu;
    const int ra[4] = {13,15,26,6}, rb[4] = {17,29,16,24};
    x0 += k0; x1 += k1;
    for (int i=0;i<4;i++){x0+=x1;x1=rotl_c(x1,ra[i]);x1^=x0;}
    x0 += k1; x1 += k2+1u;
    for (int i=0;i<4;i++){x0+=x1;x1=rotl_c(x1,rb[i]);x1^=x0;}
    x0 += k2; x1 += k0+2u;
    for (int i=0;i<4;i++){x0+=x1;x1=rotl_c(x1,ra[i]);x1^=x0;}
    x0 += k0; x1 += k1+3u;
    for (int i=0;i<4;i++){x0+=x1;x1=rotl_c(x1,rb[i]);x1^=x0;}
    x0 += k1; x1 += k2+4u;
    for (int i=0;i<4;i++){x0+=x1;x1=rotl_c(x1,ra[i]);x1^=x0;}
    x0 += k2; x1 += k0+5u;
    return ((uint64_t)x0 << 32) | x1;
}
constexpr uint64_t KS_P = tf_c(0u,42u,0u,0u);
constexpr uint64_t KC_P = tf_c(0u,42u,0u,1u);
constexpr uint32_t KS0v=(uint32_t)(KS_P>>32), KS1v=(uint32_t)KS_P;
constexpr uint32_t KC0v=(uint32_t)(KC_P>>32), KC1v=(uint32_t)KC_P;

__device__ __forceinline__ unsigned long long ffma2(unsigned long long a, unsigned long long b, unsigned long long c) {
    unsigned long long d;
    asm("fma.rn.f32x2 %0, %1, %2, %3;" : "=l"(d) : "l"(a), "l"(b), "l"(c));
    return d;
}
__device__ __forceinline__ float fold2(unsigned long long a) {
    float2 p = *(float2*)&a; return __fadd_rn(p.x, p.y);
}
__device__ __forceinline__ uint32_t rotl32(uint32_t x, int d) { return (x<<d)|(x>>(32-d)); }
__device__ __forceinline__ void tf_r(uint32_t& x0, uint32_t& x1, int r) { x0+=x1; x1=rotl32(x1,r); x1^=x0; }
__device__ __forceinline__ uint2 threefry2x32(uint32_t k0, uint32_t k1, uint32_t x0, uint32_t x1) {
    uint32_t k2 = k0^k1^0x1BD11BDAu;
    x0+=k0; x1+=k1;
    tf_r(x0,x1,13); tf_r(x0,x1,15); tf_r(x0,x1,26); tf_r(x0,x1,6);
    x0+=k1; x1+=k2+1u;
    tf_r(x0,x1,17); tf_r(x0,x1,29); tf_r(x0,x1,16); tf_r(x0,x1,24);
    x0+=k2; x1+=k0+2u;
    tf_r(x0,x1,13); tf_r(x0,x1,15); tf_r(x0,x1,26); tf_r(x0,x1,6);
    x0+=k0; x1+=k1+3u;
    tf_r(x0,x1,17); tf_r(x0,x1,29); tf_r(x0,x1,16); tf_r(x0,x1,24);
    x0+=k1; x1+=k2+4u;
    tf_r(x0,x1,13); tf_r(x0,x1,15); tf_r(x0,x1,26); tf_r(x0,x1,6);
    x0+=k2; x1+=k0+5u;
    return make_uint2(x0,x1);
}
__device__ __forceinline__ float uniform_at(uint32_t k0, uint32_t k1, uint32_t idx) {
    uint2 r = threefry2x32(k0,k1,0u,idx);
    uint32_t bits = r.x ^ r.y;
    const float TINY = 1.17549435e-38f;
    float f = __uint_as_float(0x3F800000u | (bits>>9)) - 1.0f;
    return fmaxf(TINY, __fadd_rn(f, TINY));
}
__device__ __forceinline__ float gumbel_exact(uint32_t k0, uint32_t k1, uint32_t idx) {
    float u = uniform_at(k0,k1,idx);
    return -logf(-logf(u));
}
__device__ __forceinline__ float gumbel_cheap(uint32_t k0, uint32_t k1, uint32_t idx) {
    float u = uniform_at(k0,k1,idx);
    float im = -0.69314718056f * __log2f(u);
    float s = 1.0f - u;
    float is = s * fmaf(s, fmaf(s, 0.33333333f, 0.5f), 1.0f);
    float inner = (u > 0.99609375f) ? is : im;
    return -0.69314718056f * __log2f(inner);
}

// m16n8k8 tf32 mma (baseline sm_80+ feature; f32 values passed as b32)
__device__ __forceinline__ void mma8(float& c0, float& c1, float& c2, float& c3,
                                     float a0, float a1, float a2, float a3,
                                     float b0, float b1) {
    uint32_t C0=__float_as_uint(c0),C1=__float_as_uint(c1),C2=__float_as_uint(c2),C3=__float_as_uint(c3);
    asm volatile("mma.sync.aligned.m16n8k8.row.col.f32.tf32.tf32.f32 "
        "{%0,%1,%2,%3},{%4,%5,%6,%7},{%8,%9},{%0,%1,%2,%3};"
        : "+r"(C0),"+r"(C1),"+r"(C2),"+r"(C3)
        : "r"(__float_as_uint(a0)),"r"(__float_as_uint(a1)),
          "r"(__float_as_uint(a2)),"r"(__float_as_uint(a3)),
          "r"(__float_as_uint(b0)),"r"(__float_as_uint(b1)));
    c0=__uint_as_float(C0); c1=__uint_as_float(C1); c2=__uint_as_float(C2); c3=__uint_as_float(C3);
}

__global__ __launch_bounds__(256, 3) void k_main(const float* __restrict__ x,
                                                 const float* __restrict__ ws,
                                                 const float* __restrict__ wc,
                                                 float* __restrict__ out) {
    extern __shared__ __align__(16) char smem_raw[];
    float* sXs = (float*)smem_raw;            // 32*68
    float* sXc = sXs + RPB * XP;              // 32*68
    float* sW  = sXc + RPB * XP;              // 128*68
    float* sWc = sW  + 128 * XP;              // 16*68
    float* sWW = sWc + 16 * XP;               // 128
    float* sWWc = sWW + 128;                  // 16
    float* sXN = sWWc + 16;                   // 32
    float* sCN = sXN + RPB;                   // 32
    int*   sBG = (int*)(sCN + RPB);           // 32
    int*   sSI = sBG + RPB;                   // 32
    int*   sCI = sSI + RPB;                   // 32
    float* sLossW = (float*)(sCI + RPB);      // 8
    int*   sVC = (int*)(sLossW + 8);          // 1
    int*   sFG = sVC + 1;                     // 1
    int*   sNU = sFG + 1;                     // 1
    int*   sUR = sNU + 1;                     // 32
    float* sRV = (float*)(sUR + RPB);         // 8
    int*   sRC = (int*)(sRV + 8);             // 8
    float* sMv1 = (float*)(sRC + 8);          // 4*32
    float* sMv2 = sMv1 + 128;                 // 4*32
    int*   sMc1 = (int*)(sMv2 + 128);         // 4*32

    __shared__ double sdd[256];
    __shared__ int isLast;

    int tid = threadIdx.x, lane = tid & 31, w = tid >> 5;
    int ci = tid & 15, ri = tid >> 4;
    int rowbase = blockIdx.x * RPB;

    if (tid == 0) { *sVC = 0; *sFG = 0; *sNU = 0; }

    // stage X (split halves, padded)
    const float4* gx = (const float4*)(x + (size_t)rowbase * CD);
    #pragma unroll
    for (int i = tid; i < RPB * 32; i += 256) {
        float4 v = gx[i];
        int r = i >> 5, c4 = i & 31;
        if (c4 < 16) ((float4*)(sXs + r * XP))[c4] = v;
        else         ((float4*)(sXc + r * XP))[c4 - 16] = v;
    }
    // color codebook + norms
    {
        float4 v = ((const float4*)wc)[tid];
        ((float4*)(sWc + (tid >> 4) * XP))[tid & 15] = v;
        float pd = __fadd_rn(__fadd_rn(__fmul_rn(v.x,v.x),__fmul_rn(v.y,v.y)),
                             __fadd_rn(__fmul_rn(v.z,v.z),__fmul_rn(v.w,v.w)));
        #pragma unroll
        for (int o = 8; o > 0; o >>= 1)
            pd = __fadd_rn(pd, __shfl_xor_sync(0xffffffffu, pd, o));
        if ((tid & 15) == 0) sWWc[tid >> 4] = pd;
    }
    __syncthreads();

    // bg + half norms
    {
        int r = w * 4 + (lane >> 3);
        int part = lane & 7;
        float sa = 0.f, ss = 0.f, sc = 0.f;
        #pragma unroll
        for (int j = 0; j < 8; j++) {
            float a = sXs[r * XP + part * 8 + j];
            float b = sXc[r * XP + part * 8 + j];
            sa += fabsf(a) + fabsf(b);
            ss = __fmaf_rn(a, a, ss);
            sc = __fmaf_rn(b, b, sc);
        }
        #pragma unroll
        for (int o = 1; o < 8; o <<= 1) {
            sa += __shfl_xor_sync(0xffffffffu, sa, o);
            ss += __shfl_xor_sync(0xffffffffu, ss, o);
            sc += __shfl_xor_sync(0xffffffffu, sc, o);
        }
        if (part == 0) {
            int b = (sa < 1e-6f);
            sBG[r] = b; sXN[r] = ss; sCN[r] = sc;
            if (!b) *sFG = 1;
        }
    }
    __syncthreads();
    int anyfg = *sFG;

#define EVT(j_, lg_, code_, ro_)                                              \
    {                                                                         \
        float g_ = gumbel_cheap(KS0v, KS1v, (ro_) + (uint32_t)(code_));       \
        float v_ = __fadd_rn(lg_, g_);                                        \
        v2[j_] = fmaxf(v2[j_], fminf(v_, v1[j_]));                            \
        if (v_ > v1[j_]) c1[j_] = (code_);                                    \
        v1[j_] = fmaxf(v1[j_], v_);                                           \
    }

    if (anyfg) {
        int rh = w & 1, cq = w >> 1;
        int g = lane >> 2, tig = lane & 3;
        int r0 = rh * 16 + g, r1 = r0 + 8;
        uint32_t ro0 = (uint32_t)(rowbase + r0) << 9;
        uint32_t ro1 = (uint32_t)(rowbase + r1) << 9;
        float v1[2], v2[2]; int c1[2];
        v1[0]=v1[1]=-INFINITY; v2[0]=v2[1]=-INFINITY; c1[0]=c1[1]=0x7fffffff;

        // A-fragment cache: 8 k-steps x 4 regs (rows r0/r1 fixed)
        float af[8][4];
        #pragma unroll
        for (int s = 0; s < 8; s++) {
            af[s][0] = sXs[r0 * XP + s*8 + tig];
            af[s][1] = sXs[r1 * XP + s*8 + tig];
            af[s][2] = sXs[r0 * XP + s*8 + tig + 4];
            af[s][3] = sXs[r1 * XP + s*8 + tig + 4];
        }

        for (int tile = 0; tile < 4; ++tile) {
            const float4* gw = (const float4*)(ws + (size_t)tile * 128 * HD);
            #pragma unroll
            for (int i = tid; i < 128 * 16; i += 256) {
                float4 v = gw[i];
                ((float4*)(sW + (i >> 4) * XP))[i & 15] = v;
                float pd = __fadd_rn(__fadd_rn(__fmul_rn(v.x,v.x),__fmul_rn(v.y,v.y)),
                                     __fadd_rn(__fmul_rn(v.z,v.z),__fmul_rn(v.w,v.w)));
                #pragma unroll
                for (int o = 8; o > 0; o >>= 1)
                    pd = __fadd_rn(pd, __shfl_xor_sync(0xffffffffu, pd, o));
                if ((tid & 15) == 0) sWW[i >> 4] = pd;
            }
            __syncthreads();

            #pragma unroll
            for (int nt = 0; nt < 4; nt++) {
                if (tile == 0 && cq == 0 && nt < 2) continue;  // codes 0..15 fg-excluded
                int lc = cq * 32 + nt * 8;
                float c0 = 0.f, c1v = 0.f, c2v = 0.f, c3v = 0.f;
                const float* wb = sW + (lc + g) * XP;
                #pragma unroll
                for (int s = 0; s < 8; s++) {
                    float b0 = wb[s*8 + tig];
                    float b1 = wb[s*8 + tig + 4];
                    mma8(c0, c1v, c2v, c3v, af[s][0], af[s][1], af[s][2], af[s][3], b0, b1);
                }
                int cd0 = lc + 2*tig, cd1 = cd0 + 1;
                int gc0 = tile*128 + cd0, gc1 = gc0 + 1;
                float w0 = sWW[cd0], w1 = sWW[cd1];
                EVT(0, __fmaf_rn(2.f, c0, -w0), gc0, ro0)
                EVT(0, __fmaf_rn(2.f, c1v, -w1), gc1, ro0)
                EVT(1, __fmaf_rn(2.f, c2v, -w0), gc0, ro1)
                EVT(1, __fmaf_rn(2.f, c3v, -w1), gc1, ro1)
            }
            __syncthreads();
        }
        // merge across the 4 tig lanes sharing rows r0/r1
        #pragma unroll
        for (int o = 1; o < 4; o <<= 1) {
            #pragma unroll
            for (int j = 0; j < 2; j++) {
                float ov1 = __shfl_xor_sync(0xffffffffu, v1[j], o);
                int   oc1 = __shfl_xor_sync(0xffffffffu, c1[j], o);
                float ov2 = __shfl_xor_sync(0xffffffffu, v2[j], o);
                v2[j] = fmaxf(fmaxf(v2[j], ov2), fminf(v1[j], ov1));
                if (ov1 > v1[j]) c1[j] = oc1;
                v1[j] = fmaxf(v1[j], ov1);
            }
        }
        if (tig == 0) {
            sMv1[cq*32 + r0] = v1[0]; sMv2[cq*32 + r0] = v2[0]; sMc1[cq*32 + r0] = c1[0];
            sMv1[cq*32 + r1] = v1[1]; sMv2[cq*32 + r1] = v2[1]; sMc1[cq*32 + r1] = c1[1];
        }
        __syncthreads();
        if (tid < 32) {
            int r = tid;
            float V1 = -INFINITY, V2 = -INFINITY; int C1 = 0x7fffffff;
            #pragma unroll
            for (int q = 0; q < 4; q++) {
                float a1 = sMv1[q*32 + r], a2 = sMv2[q*32 + r];
                int   ac = sMc1[q*32 + r];
                bool takeO = (a1 > V1) || (a1 == V1 && ac < C1);
                V2 = fmaxf(fmaxf(V2, a2), fminf(V1, a1));
                if (takeO) C1 = ac;
                V1 = fmaxf(V1, a1);
            }
            bool unc = !(V1 - V2 > GAPT) || sBG[r];
            if (unc) { int p = atomicAdd(sNU, 1); sUR[p] = r; }
            else sSI[r] = C1;
        }
    } else {
        {
            float4 v = ((const float4*)ws)[tid];   // codes 0..15 norms
            float pd = __fadd_rn(__fadd_rn(__fmul_rn(v.x,v.x),__fmul_rn(v.y,v.y)),
                                 __fadd_rn(__fmul_rn(v.z,v.z),__fmul_rn(v.w,v.w)));
            #pragma unroll
            for (int o = 8; o > 0; o >>= 1)
                pd = __fadd_rn(pd, __shfl_xor_sync(0xffffffffu, pd, o));
            if ((tid & 15) == 0) sWW[tid >> 4] = pd;
        }
        __syncthreads();
        if (tid < 32) {
            int r = tid;
            uint32_t ro = (uint32_t)(rowbase + r) << 9;
            float v1[1], v2[1]; int c1[1];
            v1[0] = -INFINITY; v2[0] = -INFINITY; c1[0] = 0x7fffffff;
            #pragma unroll
            for (int c = 0; c < KCO; c++) {
                float lg = -sWW[c];
                EVT(0, lg, c, ro)
            }
            if (!(v1[0] - v2[0] > GAPT)) { int p = atomicAdd(sNU, 1); sUR[p] = r; }
            else sSI[r] = c1[0];
        }
    }

    // color: exact path (thread = code ci, 2 rows)
    {
        float cbest[2]; int cbidx[2];
        #pragma unroll
        for (int q = 0; q < 2; q++) {
            int r = 16 * q + ri;
            unsigned long long a2 = 0ull;
            #pragma unroll
            for (int k4 = 0; k4 < 16; k4++) {
                ulonglong2 xv = ((const ulonglong2*)(sXc + r * XP))[k4];
                ulonglong2 wv = ((const ulonglong2*)(sWc + ci * XP))[k4];
                a2 = ffma2(xv.x, wv.x, a2);
                a2 = ffma2(xv.y, wv.y, a2);
            }
            float a = fold2(a2);
            float g = gumbel_exact(KC0v, KC1v, ((uint32_t)(rowbase + r) << 4) + (uint32_t)ci);
            float d = __fadd_rn(__fadd_rn(sCN[r], sWWc[ci]), -__fmul_rn(2.f, a));
            cbest[q] = __fadd_rn(-d, g);
            cbidx[q] = ci;
        }
        #pragma unroll
        for (int o = 8; o > 0; o >>= 1) {
            #pragma unroll
            for (int q = 0; q < 2; q++) {
                float cv = __shfl_xor_sync(0xffffffffu, cbest[q], o);
                int   cb = __shfl_xor_sync(0xffffffffu, cbidx[q], o);
                if (cv > cbest[q] || (cv == cbest[q] && cb < cbidx[q])) { cbest[q] = cv; cbidx[q] = cb; }
            }
        }
        if ((lane & 15) == 0) {
            #pragma unroll
            for (int q = 0; q < 2; q++) sCI[16 * q + ri] = cbidx[q];
        }
    }
    __syncthreads();

    // block-cooperative exact redo of uncertain rows (rare)
    int nu = *sNU;
    for (int u = 0; u < nu; u++) {
        int r = sUR[u];
        int bg = sBG[r];
        int lo = bg ? 0 : KCO, hi = bg ? KCO : KSH;
        const float* xrow = sXs + r * XP;
        float xs = sXN[r];
        uint32_t rowoff = (uint32_t)(rowbase + r) << 9;
        float bv = -INFINITY; int bc = 0x7fffffff;
        for (int c = lo + tid; c < hi; c += 256) {
            const float* wr = ws + c * HD;
            float dot = 0.f, ww = 0.f;
            #pragma unroll
            for (int j = 0; j < HD; j++) {
                float wv = wr[j];
                dot = __fmaf_rn(xrow[j], wv, dot);
                ww  = __fmaf_rn(wv, wv, ww);
            }
            float d = __fadd_rn(__fadd_rn(xs, ww), -__fmul_rn(2.f, dot));
            float g = gumbel_exact(KS0v, KS1v, rowoff + (uint32_t)c);
            float v = __fadd_rn(-d, g);
            if (v > bv || (v == bv && c < bc)) { bv = v; bc = c; }
        }
        #pragma unroll
        for (int o = 16; o > 0; o >>= 1) {
            float ov = __shfl_xor_sync(0xffffffffu, bv, o);
            int   oc = __shfl_xor_sync(0xffffffffu, bc, o);
            if (ov > bv || (ov == bv && oc < bc)) { bv = ov; bc = oc; }
        }
        if (lane == 0) { sRV[w] = bv; sRC[w] = bc; }
        __syncthreads();
        if (tid == 0) {
            float fv = sRV[0]; int fc = sRC[0];
            #pragma unroll
            for (int i = 1; i < 8; i++)
                if (sRV[i] > fv || (sRV[i] == fv && sRC[i] < fc)) { fv = sRV[i]; fc = sRC[i]; }
            sSI[r] = fc;
        }
        __syncthreads();
    }

    // outputs
    float eacc = 0.f; int vcnt = 0;
    for (int t = 0; t < 4; t++) {
        int r = w * 4 + t;
        int widx = sSI[r], cidx = sCI[r];
        size_t grow = (size_t)rowbase + r;
        float4 wv, xv;
        if (lane < 16) {
            wv = ((const float4*)(ws + widx * HD))[lane];
            xv = ((const float4*)(sXs + r * XP))[lane];
        } else {
            wv = ((const float4*)(wc + cidx * HD))[lane - 16];
            xv = ((const float4*)(sXc + r * XP))[lane - 16];
        }
        ((float4*)out)[grow * 32 + lane] = wv;
        float dx = wv.x - xv.x, dy = wv.y - xv.y, dz = wv.z - xv.z, dw = wv.w - xv.w;
        float e = dx*dx + dy*dy + dz*dz + dw*dw;
        #pragma unroll
        for (int o = 16; o > 0; o >>= 1) e += __shfl_xor_sync(0xffffffffu, e, o);
        if (lane == 0) {
            out[IDX_OFF + grow] = (float)widx;
            if (!sBG[r]) {
                atomicAdd(&g_usage_s[widx], 1);
                atomicAdd(&g_usage_c[cidx], 1);
                vcnt++; eacc += e;
            }
        }
    }
    if (lane == 0) { sLossW[w] = eacc; atomicAdd(sVC, vcnt); }
    __syncthreads();
    if (tid == 0) {
        double L = 0.0;
        #pragma unroll
        for (int i = 0; i < 8; i++) L += (double)sLossW[i];
        g_loss_part[blockIdx.x] = L;
        atomicAdd(&g_vcount, *sVC);
    }

    __threadfence();
    if (tid == 0) { int t = atomicAdd(&g_ticket, 1); isLast = (t == NBLK - 1); }
    __syncthreads();
    if (!isLast) return;
    __threadfence();

    double a = 0.0;
    for (int i = tid; i < NBLK; i += 256) a += g_loss_part[i];
    sdd[tid] = a; __syncthreads();
    for (int s = 128; s > 0; s >>= 1) { if (tid < s) sdd[tid] += sdd[tid + s]; __syncthreads(); }
    double vc = (double)g_vcount;
    if (tid == 0) out[LOSS_OFF] = (float)(1.25 * sdd[0] / (vc * 128.0));
    __syncthreads();
    double e2 = 0.0;
    for (int i = tid; i < KSH; i += 256) {
        double p = (double)g_usage_s[i] / vc;
        e2 += p * log(p + 1e-10);
        out[US_OFF + i] = (float)g_usage_s[i];
    }
    sdd[tid] = e2; __syncthreads();
    for (int s = 128; s > 0; s >>= 1) { if (tid < s) sdd[tid] += sdd[tid + s]; __syncthreads(); }
    if (tid == 0) out[PS_OFF] = (float)exp(-sdd[0]);
    __syncthreads();
    double ec = 0.0;
    if (tid < KCO) {
        double p = (double)g_usage_c[tid] / vc;
        ec = p * log(p + 1e-10);
        out[UC_OFF + tid] = (float)g_usage_c[tid];
    }
    sdd[tid] = ec; __syncthreads();
    for (int s = 128; s > 0; s >>= 1) { if (tid < s) sdd[tid] += sdd[tid + s]; __syncthreads(); }
    if (tid == 0) out[PC_OFF] = (float)exp(-sdd[0]);
    __syncthreads();
    for (int i = tid; i < KSH; i += 256) g_usage_s[i] = 0;
    if (tid < KCO) g_usage_c[tid] = 0;
    if (tid == 0) { g_vcount = 0; g_ticket = 0; }
}

#define SMEM_BYTES ((RPB*XP*2 + 128*XP + 16*XP + 128 + 16 + RPB + RPB) * 4 \
                    + (RPB + RPB + RPB + 8 + 1 + 1) * 4 + (1 + RPB + 8 + 8) * 4 \
                    + (128 + 128 + 128) * 4 + 64)

extern "C" void kernel_launch(void* const* d_in, const int* in_sizes, int n_in,
                              void* d_out, int out_size) {
    const float* x  = (const float*)d_in[0];
    const float* ws = (const float*)d_in[2];
    const float* wc = (const float*)d_in[3];
    float* out = (float*)d_out;
    cudaFuncSetAttribute(k_main, cudaFuncAttributeMaxDynamicSharedMemorySize, SMEM_BYTES);
    k_main<<<NBLK, 256, SMEM_BYTES>>>(x, ws, wc, out);
}

// round 15
// speedup vs baseline: 1.3008x; 1.0020x over previous
#include <cuda_runtime.h>
#include <stdint.h>
#include <math.h>

#define T_ROWS 65536
#define CD 128
#define HD 64
#define KSH 512
#define KCO 16
#define RPB 32
#define NBLK (T_ROWS / RPB)

#define LOSS_OFF 8388608ul
#define PS_OFF   8388609ul
#define PC_OFF   8388610ul
#define IDX_OFF  8388611ul
#define US_OFF   8454147ul
#define UC_OFF   8454659ul

#define XP 68
#define GAPT 1.0e-3f

__device__ int    g_usage_s[KSH];
__device__ int    g_usage_c[KCO];
__device__ int    g_vcount;
__device__ int    g_ticket;
__device__ double g_loss_part[NBLK];

constexpr uint32_t rotl_c(uint32_t x, int d) { return (x << d) | (x >> (32 - d)); }
constexpr uint64_t tf_c(uint32_t k0, uint32_t k1, uint32_t x0, uint32_t x1) {
    uint32_t k2 = k0 ^ k1 ^ 0x1BD11BDAu;
    const int ra[4] = {13,15,26,6}, rb[4] = {17,29,16,24};
    x0 += k0; x1 += k1;
    for (int i=0;i<4;i++){x0+=x1;x1=rotl_c(x1,ra[i]);x1^=x0;}
    x0 += k1; x1 += k2+1u;
    for (int i=0;i<4;i++){x0+=x1;x1=rotl_c(x1,rb[i]);x1^=x0;}
    x0 += k2; x1 += k0+2u;
    for (int i=0;i<4;i++){x0+=x1;x1=rotl_c(x1,ra[i]);x1^=x0;}
    x0 += k0; x1 += k1+3u;
    for (int i=0;i<4;i++){x0+=x1;x1=rotl_c(x1,rb[i]);x1^=x0;}
    x0 += k1; x1 += k2+4u;
    for (int i=0;i<4;i++){x0+=x1;x1=rotl_c(x1,ra[i]);x1^=x0;}
    x0 += k2; x1 += k0+5u;
    return ((uint64_t)x0 << 32) | x1;
}
constexpr uint64_t KS_P = tf_c(0u,42u,0u,0u);
constexpr uint64_t KC_P = tf_c(0u,42u,0u,1u);
constexpr uint32_t KS0v=(uint32_t)(KS_P>>32), KS1v=(uint32_t)KS_P;
constexpr uint32_t KC0v=(uint32_t)(KC_P>>32), KC1v=(uint32_t)KC_P;

__device__ __forceinline__ unsigned long long ffma2(unsigned long long a, unsigned long long b, unsigned long long c) {
    unsigned long long d;
    asm("fma.rn.f32x2 %0, %1, %2, %3;" : "=l"(d) : "l"(a), "l"(b), "l"(c));
    return d;
}
__device__ __forceinline__ float fold2(unsigned long long a) {
    float2 p = *(float2*)&a; return __fadd_rn(p.x, p.y);
}
__device__ __forceinline__ uint32_t rotl32(uint32_t x, int d) { return (x<<d)|(x>>(32-d)); }
__device__ __forceinline__ void tf_r(uint32_t& x0, uint32_t& x1, int r) { x0+=x1; x1=rotl32(x1,r); x1^=x0; }
__device__ __forceinline__ uint2 threefry2x32(uint32_t k0, uint32_t k1, uint32_t x0, uint32_t x1) {
    uint32_t k2 = k0^k1^0x1BD11BDAu;
    x0+=k0; x1+=k1;
    tf_r(x0,x1,13); tf_r(x0,x1,15); tf_r(x0,x1,26); tf_r(x0,x1,6);
    x0+=k1; x1+=k2+1u;
    tf_r(x0,x1,17); tf_r(x0,x1,29); tf_r(x0,x1,16); tf_r(x0,x1,24);
    x0+=k2; x1+=k0+2u;
    tf_r(x0,x1,13); tf_r(x0,x1,15); tf_r(x0,x1,26); tf_r(x0,x1,6);
    x0+=k0; x1+=k1+3u;
    tf_r(x0,x1,17); tf_r(x0,x1,29); tf_r(x0,x1,16); tf_r(x0,x1,24);
    x0+=k1; x1+=k2+4u;
    tf_r(x0,x1,13); tf_r(x0,x1,15); tf_r(x0,x1,26); tf_r(x0,x1,6);
    x0+=k2; x1+=k0+5u;
    return make_uint2(x0,x1);
}
__device__ __forceinline__ float uniform_at(uint32_t k0, uint32_t k1, uint32_t idx) {
    uint2 r = threefry2x32(k0,k1,0u,idx);
    uint32_t bits = r.x ^ r.y;
    const float TINY = 1.17549435e-38f;
    float f = __uint_as_float(0x3F800000u | (bits>>9)) - 1.0f;
    return fmaxf(TINY, __fadd_rn(f, TINY));
}
__device__ __forceinline__ float gumbel_exact(uint32_t k0, uint32_t k1, uint32_t idx) {
    float u = uniform_at(k0,k1,idx);
    return -logf(-logf(u));
}
__device__ __forceinline__ float gumbel_cheap(uint32_t k0, uint32_t k1, uint32_t idx) {
    float u = uniform_at(k0,k1,idx);
    float im = -0.69314718056f * __log2f(u);
    float s = 1.0f - u;
    float is = s * fmaf(s, fmaf(s, 0.33333333f, 0.5f), 1.0f);
    float inner = (u > 0.99609375f) ? is : im;
    return -0.69314718056f * __log2f(inner);
}

// m16n8k8 tf32 mma (baseline sm_80+ feature; f32 values passed as b32)
__device__ __forceinline__ void mma8(float& c0, float& c1, float& c2, float& c3,
                                     float a0, float a1, float a2, float a3,
                                     float b0, float b1) {
    uint32_t C0=__float_as_uint(c0),C1=__float_as_uint(c1),C2=__float_as_uint(c2),C3=__float_as_uint(c3);
    asm volatile("mma.sync.aligned.m16n8k8.row.col.f32.tf32.tf32.f32 "
        "{%0,%1,%2,%3},{%4,%5,%6,%7},{%8,%9},{%0,%1,%2,%3};"
        : "+r"(C0),"+r"(C1),"+r"(C2),"+r"(C3)
        : "r"(__float_as_uint(a0)),"r"(__float_as_uint(a1)),
          "r"(__float_as_uint(a2)),"r"(__float_as_uint(a3)),
          "r"(__float_as_uint(b0)),"r"(__float_as_uint(b1)));
    c0=__uint_as_float(C0); c1=__uint_as_float(C1); c2=__uint_as_float(C2); c3=__uint_as_float(C3);
}

__global__ __launch_bounds__(256, 3) void k_main(const float* __restrict__ x,
                                                 const float* __restrict__ ws,
                                                 const float* __restrict__ wc,
                                                 float* __restrict__ out) {
    extern __shared__ __align__(16) char smem_raw[];
    float* sXs = (float*)smem_raw;            // 32*68
    float* sXc = sXs + RPB * XP;              // 32*68
    float* sW  = sXc + RPB * XP;              // 128*68
    float* sWc = sW  + 128 * XP;              // 16*68
    float* sWW = sWc + 16 * XP;               // 128
    float* sWWc = sWW + 128;                  // 16
    float* sXN = sWWc + 16;                   // 32
    float* sCN = sXN + RPB;                   // 32
    int*   sBG = (int*)(sCN + RPB);           // 32
    int*   sSI = sBG + RPB;                   // 32
    int*   sCI = sSI + RPB;                   // 32
    float* sLossW = (float*)(sCI + RPB);      // 8
    int*   sVC = (int*)(sLossW + 8);          // 1
    int*   sFG = sVC + 1;                     // 1
    int*   sNU = sFG + 1;                     // 1
    int*   sUR = sNU + 1;                     // 32
    float* sRV = (float*)(sUR + RPB);         // 8
    int*   sRC = (int*)(sRV + 8);             // 8
    float* sMv1 = (float*)(sRC + 8);          // 4*32
    float* sMv2 = sMv1 + 128;                 // 4*32
    int*   sMc1 = (int*)(sMv2 + 128);         // 4*32

    __shared__ double sdd[256];
    __shared__ int isLast;

    int tid = threadIdx.x, lane = tid & 31, w = tid >> 5;
    int ci = tid & 15, ri = tid >> 4;
    int rowbase = blockIdx.x * RPB;

    if (tid == 0) { *sVC = 0; *sFG = 0; *sNU = 0; }

    // stage X (split halves, padded)
    const float4* gx = (const float4*)(x + (size_t)rowbase * CD);
    #pragma unroll
    for (int i = tid; i < RPB * 32; i += 256) {
        float4 v = gx[i];
        int r = i >> 5, c4 = i & 31;
        if (c4 < 16) ((float4*)(sXs + r * XP))[c4] = v;
        else         ((float4*)(sXc + r * XP))[c4 - 16] = v;
    }
    // color codebook + norms
    {
        float4 v = ((const float4*)wc)[tid];
        ((float4*)(sWc + (tid >> 4) * XP))[tid & 15] = v;
        float pd = __fadd_rn(__fadd_rn(__fmul_rn(v.x,v.x),__fmul_rn(v.y,v.y)),
                             __fadd_rn(__fmul_rn(v.z,v.z),__fmul_rn(v.w,v.w)));
        #pragma unroll
        for (int o = 8; o > 0; o >>= 1)
            pd = __fadd_rn(pd, __shfl_xor_sync(0xffffffffu, pd, o));
        if ((tid & 15) == 0) sWWc[tid >> 4] = pd;
    }
    __syncthreads();

    // bg + half norms
    {
        int r = w * 4 + (lane >> 3);
        int part = lane & 7;
        float sa = 0.f, ss = 0.f, sc = 0.f;
        #pragma unroll
        for (int j = 0; j < 8; j++) {
            float a = sXs[r * XP + part * 8 + j];
            float b = sXc[r * XP + part * 8 + j];
            sa += fabsf(a) + fabsf(b);
            ss = __fmaf_rn(a, a, ss);
            sc = __fmaf_rn(b, b, sc);
        }
        #pragma unroll
        for (int o = 1; o < 8; o <<= 1) {
            sa += __shfl_xor_sync(0xffffffffu, sa, o);
            ss += __shfl_xor_sync(0xffffffffu, ss, o);
            sc += __shfl_xor_sync(0xffffffffu, sc, o);
        }
        if (part == 0) {
            int b = (sa < 1e-6f);
            sBG[r] = b; sXN[r] = ss; sCN[r] = sc;
            if (!b) *sFG = 1;
        }
    }
    __syncthreads();
    int anyfg = *sFG;

#define EVT(j_, lg_, code_, ro_)                                              \
    {                                                                         \
        float g_ = gumbel_cheap(KS0v, KS1v, (ro_) + (uint32_t)(code_));       \
        float v_ = __fadd_rn(lg_, g_);                                        \
        v2[j_] = fmaxf(v2[j_], fminf(v_, v1[j_]));                            \
        if (v_ > v1[j_]) c1[j_] = (code_);                                    \
        v1[j_] = fmaxf(v1[j_], v_);                                           \
    }

    if (anyfg) {
        int rh = w & 1, cq = w >> 1;
        int g = lane >> 2, tig = lane & 3;
        int r0 = rh * 16 + g, r1 = r0 + 8;
        uint32_t ro0 = (uint32_t)(rowbase + r0) << 9;
        uint32_t ro1 = (uint32_t)(rowbase + r1) << 9;
        float v1[2], v2[2]; int c1[2];
        v1[0]=v1[1]=-INFINITY; v2[0]=v2[1]=-INFINITY; c1[0]=c1[1]=0x7fffffff;

        // A-fragment cache: 8 k-steps x 4 regs (rows r0/r1 fixed)
        float af[8][4];
        #pragma unroll
        for (int s = 0; s < 8; s++) {
            af[s][0] = sXs[r0 * XP + s*8 + tig];
            af[s][1] = sXs[r1 * XP + s*8 + tig];
            af[s][2] = sXs[r0 * XP + s*8 + tig + 4];
            af[s][3] = sXs[r1 * XP + s*8 + tig + 4];
        }

        for (int tile = 0; tile < 4; ++tile) {
            const float4* gw = (const float4*)(ws + (size_t)tile * 128 * HD);
            #pragma unroll
            for (int i = tid; i < 128 * 16; i += 256) {
                float4 v = gw[i];
                ((float4*)(sW + (i >> 4) * XP))[i & 15] = v;
                float pd = __fadd_rn(__fadd_rn(__fmul_rn(v.x,v.x),__fmul_rn(v.y,v.y)),
                                     __fadd_rn(__fmul_rn(v.z,v.z),__fmul_rn(v.w,v.w)));
                #pragma unroll
                for (int o = 8; o > 0; o >>= 1)
                    pd = __fadd_rn(pd, __shfl_xor_sync(0xffffffffu, pd, o));
                if ((tid & 15) == 0) sWW[i >> 4] = pd;
            }
            __syncthreads();

            #pragma unroll
            for (int nt = 0; nt < 4; nt++) {
                if (tile == 0 && cq == 0 && nt < 2) continue;  // codes 0..15 fg-excluded
                int lc = cq * 32 + nt * 8;
                float c0 = 0.f, c1v = 0.f, c2v = 0.f, c3v = 0.f;
                const float* wb = sW + (lc + g) * XP;
                #pragma unroll
                for (int s = 0; s < 8; s++) {
                    float b0 = wb[s*8 + tig];
                    float b1 = wb[s*8 + tig + 4];
                    mma8(c0, c1v, c2v, c3v, af[s][0], af[s][1], af[s][2], af[s][3], b0, b1);
                }
                int cd0 = lc + 2*tig, cd1 = cd0 + 1;
                int gc0 = tile*128 + cd0, gc1 = gc0 + 1;
                float w0 = sWW[cd0], w1 = sWW[cd1];
                EVT(0, __fmaf_rn(2.f, c0, -w0), gc0, ro0)
                EVT(0, __fmaf_rn(2.f, c1v, -w1), gc1, ro0)
                EVT(1, __fmaf_rn(2.f, c2v, -w0), gc0, ro1)
                EVT(1, __fmaf_rn(2.f, c3v, -w1), gc1, ro1)
            }
            __syncthreads();
        }
        // merge across the 4 tig lanes sharing rows r0/r1
        #pragma unroll
        for (int o = 1; o < 4; o <<= 1) {
            #pragma unroll
            for (int j = 0; j < 2; j++) {
                float ov1 = __shfl_xor_sync(0xffffffffu, v1[j], o);
                int   oc1 = __shfl_xor_sync(0xffffffffu, c1[j], o);
                float ov2 = __shfl_xor_sync(0xffffffffu, v2[j], o);
                v2[j] = fmaxf(fmaxf(v2[j], ov2), fminf(v1[j], ov1));
                if (ov1 > v1[j]) c1[j] = oc1;
                v1[j] = fmaxf(v1[j], ov1);
            }
        }
        if (tig == 0) {
            sMv1[cq*32 + r0] = v1[0]; sMv2[cq*32 + r0] = v2[0]; sMc1[cq*32 + r0] = c1[0];
            sMv1[cq*32 + r1] = v1[1]; sMv2[cq*32 + r1] = v2[1]; sMc1[cq*32 + r1] = c1[1];
        }
        __syncthreads();
        if (tid < 32) {
            int r = tid;
            float V1 = -INFINITY, V2 = -INFINITY; int C1 = 0x7fffffff;
            #pragma unroll
            for (int q = 0; q < 4; q++) {
                float a1 = sMv1[q*32 + r], a2 = sMv2[q*32 + r];
                int   ac = sMc1[q*32 + r];
                bool takeO = (a1 > V1) || (a1 == V1 && ac < C1);
                V2 = fmaxf(fmaxf(V2, a2), fminf(V1, a1));
                if (takeO) C1 = ac;
                V1 = fmaxf(V1, a1);
            }
            bool unc = !(V1 - V2 > GAPT) || sBG[r];
            if (unc) { int p = atomicAdd(sNU, 1); sUR[p] = r; }
            else sSI[r] = C1;
        }
    } else {
        {
            float4 v = ((const float4*)ws)[tid];   // codes 0..15 norms
            float pd = __fadd_rn(__fadd_rn(__fmul_rn(v.x,v.x),__fmul_rn(v.y,v.y)),
                                 __fadd_rn(__fmul_rn(v.z,v.z),__fmul_rn(v.w,v.w)));
            #pragma unroll
            for (int o = 8; o > 0; o >>= 1)
                pd = __fadd_rn(pd, __shfl_xor_sync(0xffffffffu, pd, o));
            if ((tid & 15) == 0) sWW[tid >> 4] = pd;
        }
        __syncthreads();
        if (tid < 32) {
            int r = tid;
            uint32_t ro = (uint32_t)(rowbase + r) << 9;
            float v1[1], v2[1]; int c1[1];
            v1[0] = -INFINITY; v2[0] = -INFINITY; c1[0] = 0x7fffffff;
            #pragma unroll
            for (int c = 0; c < KCO; c++) {
                float lg = -sWW[c];
                EVT(0, lg, c, ro)
            }
            if (!(v1[0] - v2[0] > GAPT)) { int p = atomicAdd(sNU, 1); sUR[p] = r; }
            else sSI[r] = c1[0];
        }
    }

    // color: exact path (thread = code ci, 2 rows)
    {
        float cbest[2]; int cbidx[2];
        #pragma unroll
        for (int q = 0; q < 2; q++) {
            int r = 16 * q + ri;
            unsigned long long a2 = 0ull;
            #pragma unroll
            for (int k4 = 0; k4 < 16; k4++) {
                ulonglong2 xv = ((const ulonglong2*)(sXc + r * XP))[k4];
                ulonglong2 wv = ((const ulonglong2*)(sWc + ci * XP))[k4];
                a2 = ffma2(xv.x, wv.x, a2);
                a2 = ffma2(xv.y, wv.y, a2);
            }
            float a = fold2(a2);
            float g = gumbel_exact(KC0v, KC1v, ((uint32_t)(rowbase + r) << 4) + (uint32_t)ci);
            float d = __fadd_rn(__fadd_rn(sCN[r], sWWc[ci]), -__fmul_rn(2.f, a));
            cbest[q] = __fadd_rn(-d, g);
            cbidx[q] = ci;
        }
        #pragma unroll
        for (int o = 8; o > 0; o >>= 1) {
            #pragma unroll
            for (int q = 0; q < 2; q++) {
                float cv = __shfl_xor_sync(0xffffffffu, cbest[q], o);
                int   cb = __shfl_xor_sync(0xffffffffu, cbidx[q], o);
                if (cv > cbest[q] || (cv == cbest[q] && cb < cbidx[q])) { cbest[q] = cv; cbidx[q] = cb; }
            }
        }
        if ((lane & 15) == 0) {
            #pragma unroll
            for (int q = 0; q < 2; q++) sCI[16 * q + ri] = cbidx[q];
        }
    }
    __syncthreads();

    // block-cooperative exact redo of uncertain rows (rare)
    int nu = *sNU;
    for (int u = 0; u < nu; u++) {
        int r = sUR[u];
        int bg = sBG[r];
        int lo = bg ? 0 : KCO, hi = bg ? KCO : KSH;
        const float* xrow = sXs + r * XP;
        float xs = sXN[r];
        uint32_t rowoff = (uint32_t)(rowbase + r) << 9;
        float bv = -INFINITY; int bc = 0x7fffffff;
        for (int c = lo + tid; c < hi; c += 256) {
            const float* wr = ws + c * HD;
            float dot = 0.f, ww = 0.f;
            #pragma unroll
            for (int j = 0; j < HD; j++) {
                float wv = wr[j];
                dot = __fmaf_rn(xrow[j], wv, dot);
                ww  = __fmaf_rn(wv, wv, ww);
            }
            float d = __fadd_rn(__fadd_rn(xs, ww), -__fmul_rn(2.f, dot));
            float g = gumbel_exact(KS0v, KS1v, rowoff + (uint32_t)c);
            float v = __fadd_rn(-d, g);
            if (v > bv || (v == bv && c < bc)) { bv = v; bc = c; }
        }
        #pragma unroll
        for (int o = 16; o > 0; o >>= 1) {
            float ov = __shfl_xor_sync(0xffffffffu, bv, o);
            int   oc = __shfl_xor_sync(0xffffffffu, bc, o);
            if (ov > bv || (ov == bv && oc < bc)) { bv = ov; bc = oc; }
        }
        if (lane == 0) { sRV[w] = bv; sRC[w] = bc; }
        __syncthreads();
        if (tid == 0) {
            float fv = sRV[0]; int fc = sRC[0];
            #pragma unroll
            for (int i = 1; i < 8; i++)
                if (sRV[i] > fv || (sRV[i] == fv && sRC[i] < fc)) { fv = sRV[i]; fc = sRC[i]; }
            sSI[r] = fc;
        }
        __syncthreads();
    }

    // outputs
    float eacc = 0.f; int vcnt = 0;
    for (int t = 0; t < 4; t++) {
        int r = w * 4 + t;
        int widx = sSI[r], cidx = sCI[r];
        size_t grow = (size_t)rowbase + r;
        float4 wv, xv;
        if (lane < 16) {
            wv = ((const float4*)(ws + widx * HD))[lane];
            xv = ((const float4*)(sXs + r * XP))[lane];
        } else {
            wv = ((const float4*)(wc + cidx * HD))[lane - 16];
            xv = ((const float4*)(sXc + r * XP))[lane - 16];
        }
        ((float4*)out)[grow * 32 + lane] = wv;
        float dx = wv.x - xv.x, dy = wv.y - xv.y, dz = wv.z - xv.z, dw = wv.w - xv.w;
        float e = dx*dx + dy*dy + dz*dz + dw*dw;
        #pragma unroll
        for (int o = 16; o > 0; o >>= 1) e += __shfl_xor_sync(0xffffffffu, e, o);
        if (lane == 0) {
            out[IDX_OFF + grow] = (float)widx;
            if (!sBG[r]) {
                atomicAdd(&g_usage_s[widx], 1);
                atomicAdd(&g_usage_c[cidx], 1);
                vcnt++; eacc += e;
            }
        }
    }
    if (lane == 0) { sLossW[w] = eacc; atomicAdd(sVC, vcnt); }
    __syncthreads();
    if (tid == 0) {
        double L = 0.0;
        #pragma unroll
        for (int i = 0; i < 8; i++) L += (double)sLossW[i];
        g_loss_part[blockIdx.x] = L;
        atomicAdd(&g_vcount, *sVC);
    }

    __threadfence();
    if (tid == 0) { int t = atomicAdd(&g_ticket, 1); isLast = (t == NBLK - 1); }
    __syncthreads();
    if (!isLast) return;
    __threadfence();

    double a = 0.0;
    for (int i = tid; i < NBLK; i += 256) a += g_loss_part[i];
    sdd[tid] = a; __syncthreads();
    for (int s = 128; s > 0; s >>= 1) { if (tid < s) sdd[tid] += sdd[tid + s]; __syncthreads(); }
    double vc = (double)g_vcount;
    if (tid == 0) out[LOSS_OFF] = (float)(1.25 * sdd[0] / (vc * 128.0));
    __syncthreads();
    double e2 = 0.0;
    for (int i = tid; i < KSH; i += 256) {
        double p = (double)g_usage_s[i] / vc;
        e2 += p * log(p + 1e-10);
        out[US_OFF + i] = (float)g_usage_s[i];
    }
    sdd[tid] = e2; __syncthreads();
    for (int s = 128; s > 0; s >>= 1) { if (tid < s) sdd[tid] += sdd[tid + s]; __syncthreads(); }
    if (tid == 0) out[PS_OFF] = (float)exp(-sdd[0]);
    __syncthreads();
    double ec = 0.0;
    if (tid < KCO) {
        double p = (double)g_usage_c[tid] / vc;
        ec = p * log(p + 1e-10);
        out[UC_OFF + tid] = (float)g_usage_c[tid];
    }
    sdd[tid] = ec; __syncthreads();
    for (int s = 128; s > 0; s >>= 1) { if (tid < s) sdd[tid] += sdd[tid + s]; __syncthreads(); }
    if (tid == 0) out[PC_OFF] = (float)exp(-sdd[0]);
    __syncthreads();
    for (int i = tid; i < KSH; i += 256) g_usage_s[i] = 0;
    if (tid < KCO) g_usage_c[tid] = 0;
    if (tid == 0) { g_vcount = 0; g_ticket = 0; }
}

#define SMEM_BYTES ((RPB*XP*2 + 128*XP + 16*XP + 128 + 16 + RPB + RPB) * 4 \
                    + (RPB + RPB + RPB + 8 + 1 + 1) * 4 + (1 + RPB + 8 + 8) * 4 \
                    + (128 + 128 + 128) * 4 + 64)

extern "C" void kernel_launch(void* const* d_in, const int* in_sizes, int n_in,
                              void* d_out, int out_size) {
    const float* x  = (const float*)d_in[0];
    const float* ws = (const float*)d_in[2];
    const float* wc = (const float*)d_in[3];
    float* out = (float*)d_out;
    cudaFuncSetAttribute(k_main, cudaFuncAttributeMaxDynamicSharedMemorySize, SMEM_BYTES);
    k_main<<<NBLK, 256, SMEM_BYTES>>>(x, ws, wc, out);
}